// round 12
// baseline (speedup 1.0000x reference)
#include <cuda_runtime.h>
#include <cuda_bf16.h>
#include <cstdint>

#define D_MODEL 1024
#define NUM_T   2048
#define BATCH   32

#define PE_ELEMS (NUM_T * D_MODEL)            // 2,097,152
#define PE_VEC4  (PE_ELEMS / 4)               // 524,288 = 2^19
#define DVEC     (D_MODEL / 4)                // 256

#define BPT     4                             // batches per thread
#define GROUPS  (BATCH / BPT)                 // 8 block-groups
#define TPB     512                           // threads per block
#define PBLOCKS (PE_VEC4 / TPB)               // 1024 position blocks per group

#define LOG2_10000 13.287712379549449f

// Fused PE+add — round-10 winner (74.8us kernel, DRAM 81.8%) with 512-thread
// blocks: identical occupancy (32 regs -> 4 blocks/SM = 2048 thr), but 2x
// contiguous footprint per block and half the CTA count for smoother waves.
// High-bit batch-group (wave sweeps one contiguous region per group),
// .cg loads (L2-only), default-policy stores (L2 writeback aggregation).
__global__ void __launch_bounds__(TPB) fused_pe_add_kernel(const float4* __restrict__ x,
                                                           float4* __restrict__ out) {
    const unsigned pb  = blockIdx.x & (PBLOCKS - 1u);     // position block 0..1023
    const unsigned g   = blockIdx.x >> 10;                // batch group 0..7 (high bits)
    const unsigned pos = pb * (unsigned)TPB + threadIdx.x;// 0..PE_VEC4-1

    const int t  = pos >> 8;                  // timestep 0..2047
    const int i0 = (int)(pos & (DVEC - 1u)) * 4;          // first column (even)
    const float ft = (float)t;

    // 10000^(-2*i/D) = 2^(i*k)
    const float k = -2.0f / (float)D_MODEL * LOG2_10000;
    float4 pe;
    pe.x = sinf(ft * exp2f((float)(i0 + 0) * k));   // even i -> sin
    pe.y = cosf(ft * exp2f((float)(i0 + 1) * k));   // odd  i -> cos
    pe.z = sinf(ft * exp2f((float)(i0 + 2) * k));
    pe.w = cosf(ft * exp2f((float)(i0 + 3) * k));

    const unsigned base = pos + g * (unsigned)(BPT * PE_VEC4);

    float4 xv[BPT];
    #pragma unroll
    for (int b = 0; b < BPT; b++)
        xv[b] = __ldcg(&x[base + (unsigned)b * PE_VEC4]);   // L2-only load

    #pragma unroll
    for (int b = 0; b < BPT; b++) {
        float4 o;
        o.x = xv[b].x + pe.x;
        o.y = xv[b].y + pe.y;
        o.z = xv[b].z + pe.z;
        o.w = xv[b].w + pe.w;
        out[base + (unsigned)b * PE_VEC4] = o;              // default store policy
    }
}

extern "C" void kernel_launch(void* const* d_in, const int* in_sizes, int n_in,
                              void* d_out, int out_size) {
    const float4* x = (const float4*)d_in[0];
    float4* out = (float4*)d_out;
    // 1024 position blocks x 8 groups = 8192 blocks x 512 threads, exact cover
    fused_pe_add_kernel<<<PBLOCKS * GROUPS, TPB>>>(x, out);
}

// round 13
// speedup vs baseline: 1.0016x; 1.0016x over previous
#include <cuda_runtime.h>
#include <cuda_bf16.h>
#include <cstdint>

#define D_MODEL 1024
#define NUM_T   2048
#define BATCH   32

#define PE_ELEMS (NUM_T * D_MODEL)            // 2,097,152
#define PE_VEC4  (PE_ELEMS / 4)               // 524,288 = 2^19
#define DVEC     (D_MODEL / 4)                // 256

#define BPT     4                             // batches per thread
#define GROUPS  (BATCH / BPT)                 // 8 block-groups
#define PBLOCKS (PE_VEC4 / 256)               // 2048 position blocks per group

#define LOG2_10000 13.287712379549449f

// FINAL: round-10 configuration — the measured optimum across 13 variants
// (kernel 74.8us, DRAM 81.8%, 6.48 TB/s = the HBM 1:1 read/write ceiling).
//  - fused PE compute (no PE table, no L2 PE traffic, single launch)
//  - one thread = one (t, d-vec4) x 4 batches (PE computed once per 4 uses)
//  - batch-group in HIGH blockIdx bits: each wave sweeps contiguous regions
//  - .cg loads (L2-only; L1 has zero reuse), default-policy stores
//  - 256-thread blocks, 32 regs, occ ~81%, exact cover, no tail
__global__ void __launch_bounds__(256) fused_pe_add_kernel(const float4* __restrict__ x,
                                                           float4* __restrict__ out) {
    const unsigned pb  = blockIdx.x & (PBLOCKS - 1u);     // position block 0..2047
    const unsigned g   = blockIdx.x >> 11;                // batch group 0..7 (high bits)
    const unsigned pos = pb * 256u + threadIdx.x;         // 0..PE_VEC4-1

    const int t  = pos >> 8;                  // timestep 0..2047
    const int i0 = (int)(pos & (DVEC - 1u)) * 4;          // first column (even)
    const float ft = (float)t;

    // 10000^(-2*i/D) = 2^(i*k)
    const float k = -2.0f / (float)D_MODEL * LOG2_10000;
    float4 pe;
    pe.x = sinf(ft * exp2f((float)(i0 + 0) * k));   // even i -> sin
    pe.y = cosf(ft * exp2f((float)(i0 + 1) * k));   // odd  i -> cos
    pe.z = sinf(ft * exp2f((float)(i0 + 2) * k));
    pe.w = cosf(ft * exp2f((float)(i0 + 3) * k));

    const unsigned base = pos + g * (unsigned)(BPT * PE_VEC4);

    float4 xv[BPT];
    #pragma unroll
    for (int b = 0; b < BPT; b++)
        xv[b] = __ldcg(&x[base + (unsigned)b * PE_VEC4]);   // L2-only load

    #pragma unroll
    for (int b = 0; b < BPT; b++) {
        float4 o;
        o.x = xv[b].x + pe.x;
        o.y = xv[b].y + pe.y;
        o.z = xv[b].z + pe.z;
        o.w = xv[b].w + pe.w;
        out[base + (unsigned)b * PE_VEC4] = o;              // default store policy
    }
}

extern "C" void kernel_launch(void* const* d_in, const int* in_sizes, int n_in,
                              void* d_out, int out_size) {
    const float4* x = (const float4*)d_in[0];
    float4* out = (float4*)d_out;
    // 2048 position blocks x 8 groups = 16384 blocks x 256 threads, exact cover
    fused_pe_add_kernel<<<PBLOCKS * GROUPS, 256>>>(x, out);
}